// round 16
// baseline (speedup 1.0000x reference)
#include <cuda_runtime.h>
#include <cuda_bf16.h>
#include <cstdint>

// Capsule routing, factorized. Fused tf32-MMA routing kernel (blog -> smem
// softmax -> sgemm -> REDG into g_S); caps as MMA (phase A) + tiled scalar
// (phase B), 256 blocks. u (32,1024,256); W (256,2048); out (32,32,64).

#define BB 32
#define II 1024
#define CC 256
#define NN 32
#define DD 64
#define ND 2048
#define ICH 16

typedef unsigned int uint;

__device__ float g_part[BB * 8 * CC];   // colsum partials
__device__ float g_V[BB * NN * CC];     // V[b][n][c]
__device__ float g_S[BB * NN * CC];     // S accumulated via REDG

__device__ __forceinline__ uint tf32c(float f) {
    uint r; asm("cvt.rna.tf32.f32 %0, %1;" : "=r"(r) : "f"(f)); return r;
}
__device__ __forceinline__ void mma_tf32(float* d, uint a0, uint a1, uint a2, uint a3,
                                         uint b0, uint b1) {
    asm("mma.sync.aligned.m16n8k8.row.col.f32.tf32.tf32.f32 "
        "{%0,%1,%2,%3},{%4,%5,%6,%7},{%8,%9},{%0,%1,%2,%3};"
        : "+f"(d[0]), "+f"(d[1]), "+f"(d[2]), "+f"(d[3])
        : "r"(a0), "r"(a1), "r"(a2), "r"(a3), "r"(b0), "r"(b1));
}
__device__ __forceinline__ uint4 cvt4(float4 v) {
    return make_uint4(tf32c(v.x), tf32c(v.y), tf32c(v.z), tf32c(v.w));
}

// ---- colsum partials ----------------------------------------------------
__global__ void k_colsum_part(const float* __restrict__ u) {
    int q = blockIdx.x, b = blockIdx.y, c = threadIdx.x;
    const float* p = u + (size_t)b * II * CC + (size_t)q * 128 * CC + c;
    float s = 0.f;
#pragma unroll 8
    for (int i = 0; i < 128; i++) s += p[(size_t)i * CC];
    g_part[(b * 8 + q) * CC + c] = s;
}

// ---- fused routing pass (REDG into g_S) ---------------------------------
#define FSM ((96 * 260 + 64 * 36) * 4)
__global__ __launch_bounds__(256) void k_fused(const float* __restrict__ u) {
    extern __shared__ uint smraw[];
    uint (*sU)[260] = (uint(*)[260])smraw;
    uint (*sV)[260] = (uint(*)[260])(smraw + 64 * 260);
    float (*sCf)[36] = (float(*)[36])(smraw + 96 * 260);

    int ich = blockIdx.x, b = blockIdx.y;
    int i0 = ich * 64;
    int t = threadIdx.x, lane = t & 31, w = t >> 5;
    int g4 = lane >> 2, j4 = lane & 3;

#pragma unroll
    for (int it = 0; it < 8; it++) {
        int idx = it * 256 + t, row = idx >> 6, c4 = idx & 63;
        float4 v = *(const float4*)(g_V + ((size_t)b * NN + row) * CC + c4 * 4);
        *(uint4*)&sV[row][c4 * 4] = cvt4(v);
    }
#pragma unroll
    for (int it = 0; it < 16; it++) {
        int idx = it * 256 + t, row = idx >> 6, c4 = idx & 63;
        float4 v = *(const float4*)(u + ((size_t)b * II + i0 + row) * CC + c4 * 4);
        *(uint4*)&sU[row][c4 * 4] = cvt4(v);
    }
    __syncthreads();

    {   // phase 1: logits[64i x 32n] = U @ V^T
        int mt1 = w >> 1, nb = (w & 1) * 2;
        float acc1[2][4] = {};
#pragma unroll 8
        for (int ks = 0; ks < 32; ks++) {
            int k0 = ks * 8;
            uint a0 = sU[mt1 * 16 + g4][k0 + j4];
            uint a1 = sU[mt1 * 16 + g4 + 8][k0 + j4];
            uint a2 = sU[mt1 * 16 + g4][k0 + j4 + 4];
            uint a3 = sU[mt1 * 16 + g4 + 8][k0 + j4 + 4];
#pragma unroll
            for (int ntl = 0; ntl < 2; ntl++) {
                int nt = nb + ntl;
                uint b0 = sV[nt * 8 + g4][k0 + j4];
                uint b1 = sV[nt * 8 + g4][k0 + j4 + 4];
                mma_tf32(acc1[ntl], a0, a1, a2, a3, b0, b1);
            }
        }
#pragma unroll
        for (int ntl = 0; ntl < 2; ntl++) {
            int nt = nb + ntl, ncol = nt * 8 + 2 * j4;
            *(float2*)&sCf[mt1 * 16 + g4][ncol] =
                make_float2(acc1[ntl][0], acc1[ntl][1]);
            *(float2*)&sCf[mt1 * 16 + g4 + 8][ncol] =
                make_float2(acc1[ntl][2], acc1[ntl][3]);
        }
    }
    __syncthreads();

    if (t < 64) {   // softmax over n
        float vv[NN];
        float m = -1e30f;
#pragma unroll
        for (int n = 0; n < NN; n++) { vv[n] = sCf[t][n]; m = fmaxf(m, vv[n]); }
        float s = 0.f;
#pragma unroll
        for (int n = 0; n < NN; n++) { vv[n] = __expf(vv[n] - m); s += vv[n]; }
        float inv = 1.0f / s;
#pragma unroll
        for (int n = 0; n < NN; n++) sCf[t][n] = vv[n] * inv;
    }
    __syncthreads();

    {   // phase 2: S += coef^T @ U_chunk (REDG)
        float acc2[2][4][4] = {};
#pragma unroll
        for (int ks = 0; ks < 8; ks++) {
            int k0 = ks * 8;
            uint a[2][4];
#pragma unroll
            for (int mt = 0; mt < 2; mt++) {
                a[mt][0] = tf32c(sCf[k0 + j4][mt * 16 + g4]);
                a[mt][1] = tf32c(sCf[k0 + j4][mt * 16 + g4 + 8]);
                a[mt][2] = tf32c(sCf[k0 + j4 + 4][mt * 16 + g4]);
                a[mt][3] = tf32c(sCf[k0 + j4 + 4][mt * 16 + g4 + 8]);
            }
#pragma unroll
            for (int ct = 0; ct < 4; ct++) {
                int c = w * 32 + ct * 8 + g4;
                uint b0 = sU[k0 + j4][c];
                uint b1 = sU[k0 + j4 + 4][c];
#pragma unroll
                for (int mt = 0; mt < 2; mt++)
                    mma_tf32(acc2[mt][ct], a[mt][0], a[mt][1], a[mt][2], a[mt][3],
                             b0, b1);
            }
        }
        float* sp = g_S + (size_t)b * NN * CC;
#pragma unroll
        for (int mt = 0; mt < 2; mt++)
#pragma unroll
            for (int ct = 0; ct < 4; ct++) {
                int cpos = w * 32 + ct * 8 + 2 * j4;
                int n0 = mt * 16 + g4;
                atomicAdd(sp + (size_t)n0 * CC + cpos,       acc2[mt][ct][0]);
                atomicAdd(sp + (size_t)n0 * CC + cpos + 1,   acc2[mt][ct][1]);
                atomicAdd(sp + (size_t)(n0 + 8) * CC + cpos,     acc2[mt][ct][2]);
                atomicAdd(sp + (size_t)(n0 + 8) * CC + cpos + 1, acc2[mt][ct][3]);
            }
    }
}

// ---- caps: out = squash(S @ W_n), V = out @ W_n^T -----------------------
// grid (n=32, bg=8), 256 thr, 4 b-rows/block. Phase A tf32 MMA on Wt[d][c].
// ALL vectorized smem bases are 16B-aligned (uint offsets ≡ 0 mod 4) and row
// strides (260, 68) are multiples of 4 elements.
#define SWT_OFF 0
#define STILE_OFF (64 * 260)                 // 16640
#define SA_OFF (STILE_OFF + 64 * 68)         // 20992
#define SDT_OFF (SA_OFF + 8 * 260)           // 23072
#define SOB_OFF (SDT_OFF + 2 * 64 * 13)      // 24736 (mod 4 == 0)
#define SRED_OFF (SOB_OFF + 4 * 68)          // 25008
#define CAPS_SM ((SRED_OFF + 16) * 4)
__global__ __launch_bounds__(256) void k_caps(const float* __restrict__ W,
                                              int mode, float* __restrict__ dout) {
    extern __shared__ uint csm[];
    uint (*sWt)[260] = (uint(*)[260])(csm + SWT_OFF);    // tf32 W^T [64d][256c]
    uint (*sTile)[68] = (uint(*)[68])(csm + STILE_OFF);  // scratch [64c][64d]
    uint (*sA)[260] = (uint(*)[260])(csm + SA_OFF);      // tf32 S [8b][256c]
    float* sDt = (float*)(csm + SDT_OFF);                // [2kh][64d][13]
    float (*sOb)[68] = (float(*)[68])(csm + SOB_OFF);    // O [4b][64d]
    float* sRed = (float*)(csm + SRED_OFF);

    int n = blockIdx.x, b0 = blockIdx.y * 4;
    int t = threadIdx.x, lane = t & 31, w = t >> 5;
    int g4 = lane >> 2, j4 = lane & 3;

    // S (or s0) rows -> sA tf32; zero pad rows; manage g_S zeroing
    if (mode == 0) {
#pragma unroll
        for (int bl = 0; bl < 4; bl++) {
            float s = 0.f;
#pragma unroll 4
            for (int q = 0; q < 8; q++) s += g_part[((b0 + bl) * 8 + q) * CC + t];
            sA[bl][t] = tf32c(s * (1.0f / 32.0f));
            g_S[((size_t)(b0 + bl) * NN + n) * CC + t] = 0.f;
        }
    } else {
#pragma unroll
        for (int bl = 0; bl < 4; bl++) {
            size_t off = ((size_t)(b0 + bl) * NN + n) * CC + t;
            sA[bl][t] = tf32c(g_S[off]);
            if (mode == 1) g_S[off] = 0.f;
        }
    }
#pragma unroll
    for (int r = 0; r < 4; r++) sA[4 + r][t] = 0u;

    // W_n slice -> sWt[d][c] via 4 transposed 64x64 tiles
#pragma unroll
    for (int ct = 0; ct < 4; ct++) {
#pragma unroll
        for (int it = 0; it < 4; it++) {
            int idx = it * 256 + t, r = idx >> 4, d4 = (idx & 15) * 4;
            float4 v = *(const float4*)(W + (size_t)(ct * 64 + r) * ND + n * DD + d4);
            *(uint4*)&sTile[r][d4] = cvt4(v);
        }
        __syncthreads();
#pragma unroll
        for (int it = 0; it < 4; it++) {
            int idx = it * 256 + t, dr = idx >> 4, c4 = (idx & 15) * 4;
            uint4 vv;
            vv.x = sTile[c4 + 0][dr]; vv.y = sTile[c4 + 1][dr];
            vv.z = sTile[c4 + 2][dr]; vv.w = sTile[c4 + 3][dr];
            *(uint4*)&sWt[dr][ct * 64 + c4] = vv;
        }
        __syncthreads();
    }

    // phase A: Dt[d][b] = W^T . S^T  (8 warps: 4 m-tiles x 2 k-halves)
    {
        int mt = w & 3, kh = w >> 2;
        float acc[4] = {};
#pragma unroll
        for (int ks = 0; ks < 16; ks++) {
            int k0 = kh * 128 + ks * 8;
            uint a0 = sWt[mt * 16 + g4][k0 + j4];
            uint a1 = sWt[mt * 16 + g4 + 8][k0 + j4];
            uint a2 = sWt[mt * 16 + g4][k0 + j4 + 4];
            uint a3 = sWt[mt * 16 + g4 + 8][k0 + j4 + 4];
            uint b0f = sA[g4][k0 + j4];
            uint b1f = sA[g4][k0 + j4 + 4];
            mma_tf32(acc, a0, a1, a2, a3, b0f, b1f);
        }
        float* sD = sDt + (size_t)kh * 64 * 13;
        sD[(mt * 16 + g4) * 13 + 2 * j4] = acc[0];
        sD[(mt * 16 + g4) * 13 + 2 * j4 + 1] = acc[1];
        sD[(mt * 16 + g4 + 8) * 13 + 2 * j4] = acc[2];
        sD[(mt * 16 + g4 + 8) * 13 + 2 * j4 + 1] = acc[3];
    }
    __syncthreads();

    // combine k-halves + squash
    int d = t & 63, bl = t >> 6;
    float x = sDt[d * 13 + bl] + sDt[(64 + d) * 13 + bl];
    float sq = x * x;
#pragma unroll
    for (int off = 16; off; off >>= 1) sq += __shfl_xor_sync(0xffffffffu, sq, off);
    if (lane == 0) sRed[w] = sq;
    __syncthreads();
    float f = rsqrtf(sRed[2 * bl] + sRed[2 * bl + 1] + 1e-7f);
    float o = x * f;
    if (mode == 2) {
        dout[((size_t)(b0 + bl) * NN + n) * DD + d] = o;
        return;
    }
    sOb[bl][d] = o;
    __syncthreads();

    // phase B: V[b][c] = sum_d O[b][d] Wt[d][c]  (thread: b, 4 c)
    {
        int c0 = (t & 63) * 4;
        float av0 = 0.f, av1 = 0.f, av2 = 0.f, av3 = 0.f;
#pragma unroll
        for (int dq = 0; dq < 16; dq++) {
            float4 o4 = *(float4*)&sOb[bl][dq * 4];
            float4 w0 = *(const float4*)((const float*)&sWt[dq * 4 + 0][c0]);
            float4 w1 = *(const float4*)((const float*)&sWt[dq * 4 + 1][c0]);
            float4 w2 = *(const float4*)((const float*)&sWt[dq * 4 + 2][c0]);
            float4 w3 = *(const float4*)((const float*)&sWt[dq * 4 + 3][c0]);
            av0 += o4.x * w0.x + o4.y * w1.x + o4.z * w2.x + o4.w * w3.x;
            av1 += o4.x * w0.y + o4.y * w1.y + o4.z * w2.y + o4.w * w3.y;
            av2 += o4.x * w0.z + o4.y * w1.z + o4.z * w2.z + o4.w * w3.z;
            av3 += o4.x * w0.w + o4.y * w1.w + o4.z * w2.w + o4.w * w3.w;
        }
        *(float4*)(g_V + ((size_t)(b0 + bl) * NN + n) * CC + c0) =
            make_float4(av0, av1, av2, av3);
    }
}

// ---------------------------------------------------------------------------
extern "C" void kernel_launch(void* const* d_in, const int* in_sizes, int n_in,
                              void* d_out, int out_size) {
    const float* u = (const float*)d_in[0];
    const float* W = (const float*)d_in[1];
    if (n_in >= 2 && in_sizes[0] == CC * ND) {
        u = (const float*)d_in[1];
        W = (const float*)d_in[0];
    }
    float* out = (float*)d_out;

    cudaFuncSetAttribute(k_caps, cudaFuncAttributeMaxDynamicSharedMemorySize, CAPS_SM);
    cudaFuncSetAttribute(k_fused, cudaFuncAttributeMaxDynamicSharedMemorySize, FSM);

    k_colsum_part<<<dim3(8, BB), 256>>>(u);
    k_caps<<<dim3(NN, 8), 256, CAPS_SM>>>(W, 0, nullptr);   // out0 -> V0, zero g_S

    for (int pass = 0; pass < 2; pass++) {
        k_fused<<<dim3(ICH, BB), 256, FSM>>>(u);            // REDG into g_S
        k_caps<<<dim3(NN, 8), 256, CAPS_SM>>>(W, pass == 0 ? 1 : 2,
                                              pass == 0 ? nullptr : out);
    }
}